// round 2
// baseline (speedup 1.0000x reference)
#include <cuda_runtime.h>
#include <mma.h>
#include <cstdint>

using namespace nvcuda;

// ---------------------------------------------------------------------------
// Problem dims (fixed): B=2, N=2048, M=1024, C=1024, H=16, D=64, HID=4096
// ---------------------------------------------------------------------------

// Scratch (static __device__ arrays; allocation APIs are forbidden)
__device__ float g_ln  [4096u * 1024u];        // LN output (reused 3x)
__device__ float g_qkv [4096u * 3072u];        // qkv projection
__device__ float g_q   [4096u * 1024u];        // cross q
__device__ float g_kv  [2048u * 2048u];        // cross kv
__device__ float g_S   [134217728ull];         // attention scores (2*16*2048*2048)
__device__ float g_attn[4096u * 1024u];        // attention output
__device__ float g_x1  [4096u * 1024u];
__device__ float g_x2  [4096u * 1024u];
__device__ float g_mid [4096u * 4096u];        // MLP hidden

// ---------------------------------------------------------------------------
// LayerNorm: one block per row
// ---------------------------------------------------------------------------
__global__ __launch_bounds__(256) void ln_kernel(const float* __restrict__ x,
                                                 float* __restrict__ out, int cols)
{
    long long base = (long long)blockIdx.x * cols;
    float s = 0.f, ss = 0.f;
    for (int i = threadIdx.x; i < cols; i += 256) {
        float v = x[base + i];
        s += v; ss += v * v;
    }
    __shared__ float shs[32], shq[32];
    for (int o = 16; o; o >>= 1) {
        s  += __shfl_xor_sync(0xffffffffu, s,  o);
        ss += __shfl_xor_sync(0xffffffffu, ss, o);
    }
    int w = threadIdx.x >> 5, l = threadIdx.x & 31;
    if (l == 0) { shs[w] = s; shq[w] = ss; }
    __syncthreads();
    if (w == 0) {
        float a = (l < 8) ? shs[l] : 0.f;
        float b = (l < 8) ? shq[l] : 0.f;
        for (int o = 4; o; o >>= 1) {
            a += __shfl_xor_sync(0xffffffffu, a, o);
            b += __shfl_xor_sync(0xffffffffu, b, o);
        }
        if (l == 0) { shs[0] = a; shq[0] = b; }
    }
    __syncthreads();
    float mean = shs[0] * (1.0f / cols);
    float var  = shq[0] * (1.0f / cols) - mean * mean;
    float inv  = rsqrtf(var + 1e-6f);
    for (int i = threadIdx.x; i < cols; i += 256)
        out[base + i] = (x[base + i] - mean) * inv;
}

// ---------------------------------------------------------------------------
// Row softmax (scale already applied in the S GEMM's alpha)
// ---------------------------------------------------------------------------
template <int L>
__global__ __launch_bounds__(256) void softmax_kernel(float* __restrict__ S)
{
    constexpr int T = 256;
    constexpr int PER = L / T;
    float* row = S + (long long)blockIdx.x * L;
    float v[PER];
    float m = -1e30f;
#pragma unroll
    for (int i = 0; i < PER; i++) { v[i] = row[threadIdx.x + i * T]; m = fmaxf(m, v[i]); }

    __shared__ float sh[32];
    for (int o = 16; o; o >>= 1) m = fmaxf(m, __shfl_xor_sync(0xffffffffu, m, o));
    int w = threadIdx.x >> 5, l = threadIdx.x & 31;
    if (l == 0) sh[w] = m;
    __syncthreads();
    if (w == 0) {
        float t = (l < 8) ? sh[l] : -1e30f;
        for (int o = 4; o; o >>= 1) t = fmaxf(t, __shfl_xor_sync(0xffffffffu, t, o));
        if (l == 0) sh[0] = t;
    }
    __syncthreads();
    m = sh[0];
    __syncthreads();

    float s = 0.f;
#pragma unroll
    for (int i = 0; i < PER; i++) { v[i] = __expf(v[i] - m); s += v[i]; }
    for (int o = 16; o; o >>= 1) s += __shfl_xor_sync(0xffffffffu, s, o);
    if (l == 0) sh[w] = s;
    __syncthreads();
    if (w == 0) {
        float t = (l < 8) ? sh[l] : 0.f;
        for (int o = 4; o; o >>= 1) t += __shfl_xor_sync(0xffffffffu, t, o);
        if (l == 0) sh[0] = t;
    }
    __syncthreads();
    float inv = 1.0f / sh[0];
#pragma unroll
    for (int i = 0; i < PER; i++) row[threadIdx.x + i * T] = v[i] * inv;
}

// ---------------------------------------------------------------------------
// Elementwise epilogue: out = [res +] gelu?(C + bias)
// ---------------------------------------------------------------------------
__global__ void epilogue_kernel(const float* __restrict__ Cin, const float* __restrict__ bias,
                                const float* __restrict__ res, float* __restrict__ out,
                                int ncols, int dogelu)
{
    int col = blockIdx.x * blockDim.x + threadIdx.x;
    if (col >= ncols) return;
    long long idx = (long long)blockIdx.y * ncols + col;
    float v = Cin[idx];
    if (bias) v += bias[col];
    if (dogelu) {
        float xx = v;
        float t = 0.7978845608028654f * (xx + 0.044715f * xx * xx * xx);
        v = 0.5f * xx * (1.0f + tanhf(t));
    }
    if (res) v += res[idx];
    out[idx] = v;
}

// ---------------------------------------------------------------------------
// Generic batched tf32 WMMA GEMM:  C = alpha * A @ B(^T)
//   A:[Mt,K] row-major stride lda, B:[K,N] (or [N,K] if TRANSB) stride ldb,
//   C:[Mt,N] stride ldc.  Per blockIdx.z: b=z/nH, h=z%nH base offsets.
//   Grid: (N/BN, Mt/BM, Z). All dims must divide exactly (they do here).
// ---------------------------------------------------------------------------
template <int BM, int BN, int BK, bool TRANSB, int WR, int WC>
__global__ __launch_bounds__(32 * WR * WC) void gemm_tf32(
    const float* __restrict__ A, const float* __restrict__ Bm, float* __restrict__ C,
    int K, int lda, int ldb, int ldc,
    long long sAb, long long sAh, long long sBb, long long sBh,
    long long sCb, long long sCh, int nH, float alpha)
{
    constexpr int T   = 32 * WR * WC;
    constexpr int AP  = BK + 4;                       // As pitch
    constexpr int BP  = TRANSB ? (BK + 4) : (BN + 4); // Bs pitch
    constexpr int WM  = BM / WR, WN = BN / WC;
    constexpr int FM  = WM / 16, FN = WN / 16;
    constexpr int ASZ = BM * AP;
    constexpr int BSZ = TRANSB ? BN * (BK + 4) : BK * (BN + 4);
    constexpr int LA  = BM * BK / (4 * T);
    constexpr int LB  = (TRANSB ? BN * BK : BK * BN) / (4 * T);

    __shared__ float As[2][ASZ];
    __shared__ float Bs[2][BSZ];

    const int tid = threadIdx.x;
    const int z = blockIdx.z;
    const int bb = z / nH, hh = z % nH;

    const float* Ab = A + bb * sAb + hh * sAh + (long long)blockIdx.y * BM * lda;
    const float* Bb = Bm + bb * sBb + hh * sBh +
                      (TRANSB ? (long long)blockIdx.x * BN * ldb : (long long)blockIdx.x * BN);
    float* Cb = C + bb * sCb + hh * sCh + (long long)blockIdx.y * BM * ldc + (long long)blockIdx.x * BN;

    float4 ra[LA], rb[LB];

    auto ldgA = [&](int kt) {
#pragma unroll
        for (int i = 0; i < LA; i++) {
            int idx = tid + i * T;
            int row = idx / (BK / 4);
            int c4  = idx % (BK / 4);
            ra[i] = *reinterpret_cast<const float4*>(Ab + (long long)row * lda + kt * BK + c4 * 4);
        }
    };
    auto ldgB = [&](int kt) {
#pragma unroll
        for (int i = 0; i < LB; i++) {
            int idx = tid + i * T;
            if constexpr (TRANSB) {
                int row = idx / (BK / 4);
                int c4  = idx % (BK / 4);
                rb[i] = *reinterpret_cast<const float4*>(Bb + (long long)row * ldb + kt * BK + c4 * 4);
            } else {
                int row = idx / (BN / 4);
                int c4  = idx % (BN / 4);
                rb[i] = *reinterpret_cast<const float4*>(Bb + (long long)(kt * BK + row) * ldb + c4 * 4);
            }
        }
    };
    auto stsA = [&](int buf) {
#pragma unroll
        for (int i = 0; i < LA; i++) {
            int idx = tid + i * T;
            int row = idx / (BK / 4);
            int c4  = idx % (BK / 4);
            float* p = &As[buf][row * AP + c4 * 4];
            p[0] = wmma::__float_to_tf32(ra[i].x);
            p[1] = wmma::__float_to_tf32(ra[i].y);
            p[2] = wmma::__float_to_tf32(ra[i].z);
            p[3] = wmma::__float_to_tf32(ra[i].w);
        }
    };
    auto stsB = [&](int buf) {
#pragma unroll
        for (int i = 0; i < LB; i++) {
            int idx = tid + i * T;
            int row, c4;
            if constexpr (TRANSB) { row = idx / (BK / 4); c4 = idx % (BK / 4); }
            else                  { row = idx / (BN / 4); c4 = idx % (BN / 4); }
            float* p = &Bs[buf][row * BP + c4 * 4];
            p[0] = wmma::__float_to_tf32(rb[i].x);
            p[1] = wmma::__float_to_tf32(rb[i].y);
            p[2] = wmma::__float_to_tf32(rb[i].z);
            p[3] = wmma::__float_to_tf32(rb[i].w);
        }
    };

    const int w = tid >> 5;
    const int wr = w / WC, wc = w % WC;
    const int rbase = wr * WM, cbase = wc * WN;

    wmma::fragment<wmma::accumulator, 16, 16, 8, float> acc[FM][FN];
#pragma unroll
    for (int i = 0; i < FM; i++)
#pragma unroll
        for (int j = 0; j < FN; j++) wmma::fill_fragment(acc[i][j], 0.0f);

    const int KT = K / BK;
    ldgA(0); ldgB(0); stsA(0); stsB(0);
    __syncthreads();

    for (int kt = 0; kt < KT; kt++) {
        const int cur = kt & 1;
        if (kt + 1 < KT) { ldgA(kt + 1); ldgB(kt + 1); }
#pragma unroll
        for (int kk = 0; kk < BK; kk += 8) {
            wmma::fragment<wmma::matrix_a, 16, 16, 8, wmma::precision::tf32, wmma::row_major> af[FM];
#pragma unroll
            for (int i = 0; i < FM; i++)
                wmma::load_matrix_sync(af[i], &As[cur][(rbase + i * 16) * AP + kk], AP);
#pragma unroll
            for (int j = 0; j < FN; j++) {
                if constexpr (TRANSB) {
                    wmma::fragment<wmma::matrix_b, 16, 16, 8, wmma::precision::tf32, wmma::col_major> bf;
                    wmma::load_matrix_sync(bf, &Bs[cur][(cbase + j * 16) * BP + kk], BP);
#pragma unroll
                    for (int i = 0; i < FM; i++) wmma::mma_sync(acc[i][j], af[i], bf, acc[i][j]);
                } else {
                    wmma::fragment<wmma::matrix_b, 16, 16, 8, wmma::precision::tf32, wmma::row_major> bf;
                    wmma::load_matrix_sync(bf, &Bs[cur][kk * BP + cbase + j * 16], BP);
#pragma unroll
                    for (int i = 0; i < FM; i++) wmma::mma_sync(acc[i][j], af[i], bf, acc[i][j]);
                }
            }
        }
        if (kt + 1 < KT) { stsA((kt + 1) & 1); stsB((kt + 1) & 1); }
        __syncthreads();
    }

#pragma unroll
    for (int i = 0; i < FM; i++)
#pragma unroll
        for (int j = 0; j < FN; j++) {
#pragma unroll
            for (int e = 0; e < acc[i][j].num_elements; e++) acc[i][j].x[e] *= alpha;
            wmma::store_matrix_sync(Cb + (long long)(rbase + i * 16) * ldc + cbase + j * 16,
                                    acc[i][j], ldc, wmma::mem_row_major);
        }
}

// ---------------------------------------------------------------------------
// Host side
// ---------------------------------------------------------------------------
static float* devptr(const void* symbol)
{
    void* p = nullptr;
    cudaGetSymbolAddress(&p, symbol);
    return (float*)p;
}

extern "C" void kernel_launch(void* const* d_in, const int* in_sizes, int n_in,
                              void* d_out, int out_size)
{
    const float* x    = (const float*)d_in[0];
    const float* ctx  = (const float*)d_in[1];
    const float* Wqkv = (const float*)d_in[2];
    const float* bqkv = (const float*)d_in[3];
    const float* Wos  = (const float*)d_in[4];
    const float* bos  = (const float*)d_in[5];
    const float* Wq   = (const float*)d_in[6];
    const float* bq   = (const float*)d_in[7];
    const float* Wkv  = (const float*)d_in[8];
    const float* bkv  = (const float*)d_in[9];
    const float* Woc  = (const float*)d_in[10];
    const float* boc  = (const float*)d_in[11];
    const float* W1   = (const float*)d_in[12];
    const float* b1   = (const float*)d_in[13];
    const float* W2   = (const float*)d_in[14];
    const float* b2   = (const float*)d_in[15];
    float* out = (float*)d_out;

    float* ln   = devptr(g_ln);
    float* qkv  = devptr(g_qkv);
    float* q    = devptr(g_q);
    float* kv   = devptr(g_kv);
    float* S    = devptr(g_S);
    float* attn = devptr(g_attn);
    float* x1   = devptr(g_x1);
    float* x2   = devptr(g_x2);
    float* mid  = devptr(g_mid);

    const int TQ = 4096;   // B*N tokens
    const int TKV = 2048;  // B*M tokens

    // ---- self-attention block ----
    ln_kernel<<<TQ, 256>>>(x, ln, 1024);

    // qkv = ln @ Wqkv  (4096 x 3072 x 1024)
    gemm_tf32<128, 128, 16, false, 2, 4><<<dim3(3072 / 128, TQ / 128, 1), 256>>>(
        ln, Wqkv, qkv, 1024, 1024, 3072, 3072, 0, 0, 0, 0, 0, 0, 1, 1.0f);
    epilogue_kernel<<<dim3(3072 / 256, TQ), 256>>>(qkv, bqkv, nullptr, qkv, 3072, 0);

    // S[b,h] = (Q K^T) * 1/8 : per (b,h) 2048x2048, K=64
    gemm_tf32<128, 128, 16, true, 2, 4><<<dim3(2048 / 128, 2048 / 128, 32), 256>>>(
        qkv, qkv + 1024, S, 64, 3072, 3072, 2048,
        (long long)2048 * 3072, 64, (long long)2048 * 3072, 64,
        (long long)16 * 2048 * 2048, (long long)2048 * 2048, 16, 0.125f);
    softmax_kernel<2048><<<32 * 2048, 256>>>(S);

    // attn = P @ V : per (b,h) 2048x64, K=2048
    gemm_tf32<128, 64, 16, false, 4, 2><<<dim3(1, 2048 / 128, 32), 256>>>(
        S, qkv + 2048, attn, 2048, 2048, 3072, 1024,
        (long long)16 * 2048 * 2048, (long long)2048 * 2048,
        (long long)2048 * 3072, 64,
        (long long)2048 * 1024, 64, 16, 1.0f);

    // x1 = x + attn @ Wos + bos
    gemm_tf32<128, 128, 16, false, 2, 4><<<dim3(1024 / 128, TQ / 128, 1), 256>>>(
        attn, Wos, x1, 1024, 1024, 1024, 1024, 0, 0, 0, 0, 0, 0, 1, 1.0f);
    epilogue_kernel<<<dim3(1024 / 256, TQ), 256>>>(x1, bos, x, x1, 1024, 0);

    // ---- cross-attention block ----
    ln_kernel<<<TQ, 256>>>(x1, ln, 1024);

    gemm_tf32<128, 128, 16, false, 2, 4><<<dim3(1024 / 128, TQ / 128, 1), 256>>>(
        ln, Wq, q, 1024, 1024, 1024, 1024, 0, 0, 0, 0, 0, 0, 1, 1.0f);
    epilogue_kernel<<<dim3(1024 / 256, TQ), 256>>>(q, bq, nullptr, q, 1024, 0);

    gemm_tf32<128, 128, 16, false, 2, 4><<<dim3(2048 / 128, TKV / 128, 1), 256>>>(
        ctx, Wkv, kv, 1024, 1024, 2048, 2048, 0, 0, 0, 0, 0, 0, 1, 1.0f);
    epilogue_kernel<<<dim3(2048 / 256, TKV), 256>>>(kv, bkv, nullptr, kv, 2048, 0);

    // S[b,h] = (q k^T) * 1/8 : per (b,h) 2048x1024, K=64
    gemm_tf32<128, 128, 16, true, 2, 4><<<dim3(1024 / 128, 2048 / 128, 32), 256>>>(
        q, kv, S, 64, 1024, 2048, 1024,
        (long long)2048 * 1024, 64, (long long)1024 * 2048, 64,
        (long long)16 * 2048 * 1024, (long long)2048 * 1024, 16, 0.125f);
    softmax_kernel<1024><<<32 * 2048, 256>>>(S);

    // attn = P @ V : per (b,h) 2048x64, K=1024
    gemm_tf32<128, 64, 16, false, 4, 2><<<dim3(1, 2048 / 128, 32), 256>>>(
        S, kv + 1024, attn, 1024, 1024, 2048, 1024,
        (long long)16 * 2048 * 1024, (long long)2048 * 1024,
        (long long)1024 * 2048, 64,
        (long long)2048 * 1024, 64, 16, 1.0f);

    // x2 = x1 + attn @ Woc + boc
    gemm_tf32<128, 128, 16, false, 2, 4><<<dim3(1024 / 128, TQ / 128, 1), 256>>>(
        attn, Woc, x2, 1024, 1024, 1024, 1024, 0, 0, 0, 0, 0, 0, 1, 1.0f);
    epilogue_kernel<<<dim3(1024 / 256, TQ), 256>>>(x2, boc, x1, x2, 1024, 0);

    // ---- MLP ----
    ln_kernel<<<TQ, 256>>>(x2, ln, 1024);

    gemm_tf32<128, 128, 16, false, 2, 4><<<dim3(4096 / 128, TQ / 128, 1), 256>>>(
        ln, W1, mid, 1024, 1024, 4096, 4096, 0, 0, 0, 0, 0, 0, 1, 1.0f);
    epilogue_kernel<<<dim3(4096 / 256, TQ), 256>>>(mid, b1, nullptr, mid, 4096, 1);

    gemm_tf32<128, 128, 16, false, 2, 4><<<dim3(1024 / 128, TQ / 128, 1), 256>>>(
        mid, W2, out, 4096, 4096, 1024, 1024, 0, 0, 0, 0, 0, 0, 1, 1.0f);
    epilogue_kernel<<<dim3(1024 / 256, TQ), 256>>>(out, b2, x2, out, 1024, 0);
}

// round 3
// speedup vs baseline: 1.4205x; 1.4205x over previous
#include <cuda_runtime.h>
#include <cuda_bf16.h>
#include <mma.h>
#include <cstdint>

using namespace nvcuda;

// Dims: B=2, N=2048, M=1024, C=1024, H=16, D=64, HID=4096
// Tokens: TQ = 4096 (B*N), TKV = 2048 (B*M)

// ---------------- scratch ----------------
__device__ float          g_ln  [4096u * 1024u];
__device__ __nv_bfloat16  g_qkv [4096u * 3072u];   // bf16 q|k|v
__device__ __nv_bfloat16  g_q   [4096u * 1024u];   // bf16 cross q
__device__ __nv_bfloat16  g_kv  [2048u * 2048u];   // bf16 cross k|v
__device__ float          g_attn[4096u * 1024u];
__device__ float          g_x1  [4096u * 1024u];
__device__ float          g_x2  [4096u * 1024u];
__device__ float          g_mid [4096u * 4096u];

// ---------------- LayerNorm ----------------
__global__ __launch_bounds__(256) void ln_kernel(const float* __restrict__ x,
                                                 float* __restrict__ out, int cols)
{
    long long base = (long long)blockIdx.x * cols;
    float s = 0.f, ss = 0.f;
    for (int i = threadIdx.x; i < cols; i += 256) {
        float v = x[base + i];
        s += v; ss += v * v;
    }
    __shared__ float shs[32], shq[32];
    for (int o = 16; o; o >>= 1) {
        s  += __shfl_xor_sync(0xffffffffu, s,  o);
        ss += __shfl_xor_sync(0xffffffffu, ss, o);
    }
    int w = threadIdx.x >> 5, l = threadIdx.x & 31;
    if (l == 0) { shs[w] = s; shq[w] = ss; }
    __syncthreads();
    if (w == 0) {
        float a = (l < 8) ? shs[l] : 0.f;
        float b = (l < 8) ? shq[l] : 0.f;
        for (int o = 4; o; o >>= 1) {
            a += __shfl_xor_sync(0xffffffffu, a, o);
            b += __shfl_xor_sync(0xffffffffu, b, o);
        }
        if (l == 0) { shs[0] = a; shq[0] = b; }
    }
    __syncthreads();
    float mean = shs[0] * (1.0f / cols);
    float var  = shq[0] * (1.0f / cols) - mean * mean;
    float inv  = rsqrtf(var + 1e-6f);
    for (int i = threadIdx.x; i < cols; i += 256)
        out[base + i] = (x[base + i] - mean) * inv;
}

// ---------------- mma / ldmatrix helpers ----------------
__device__ __forceinline__ void mma16816(float c[4], uint32_t a0, uint32_t a1,
                                         uint32_t a2, uint32_t a3,
                                         uint32_t b0, uint32_t b1)
{
    asm volatile("mma.sync.aligned.m16n8k16.row.col.f32.bf16.bf16.f32 "
                 "{%0,%1,%2,%3}, {%4,%5,%6,%7}, {%8,%9}, {%0,%1,%2,%3};"
                 : "+f"(c[0]), "+f"(c[1]), "+f"(c[2]), "+f"(c[3])
                 : "r"(a0), "r"(a1), "r"(a2), "r"(a3), "r"(b0), "r"(b1));
}
__device__ __forceinline__ void ldsm4(uint32_t& r0, uint32_t& r1, uint32_t& r2,
                                      uint32_t& r3, const void* p)
{
    uint32_t a = (uint32_t)__cvta_generic_to_shared(p);
    asm volatile("ldmatrix.sync.aligned.m8n8.x4.shared.b16 {%0,%1,%2,%3}, [%4];"
                 : "=r"(r0), "=r"(r1), "=r"(r2), "=r"(r3) : "r"(a));
}
__device__ __forceinline__ void ldsm4t(uint32_t& r0, uint32_t& r1, uint32_t& r2,
                                       uint32_t& r3, const void* p)
{
    uint32_t a = (uint32_t)__cvta_generic_to_shared(p);
    asm volatile("ldmatrix.sync.aligned.m8n8.x4.trans.shared.b16 {%0,%1,%2,%3}, [%4];"
                 : "=r"(r0), "=r"(r1), "=r"(r2), "=r"(r3) : "r"(a));
}
__device__ __forceinline__ uint32_t packbf2(float lo, float hi)
{
    __nv_bfloat162 h = __floats2bfloat162_rn(lo, hi);
    return *reinterpret_cast<uint32_t*>(&h);
}

// ---------------- fused flash attention (bf16, FA2 layout) ----------------
// block: 128 threads (4 warps), 128 q rows (32/warp), 64-key tiles, D=64.
// grid: (q_tiles_per_bh, B*H)
__global__ __launch_bounds__(128) void flash_kernel(
    const __nv_bfloat16* __restrict__ Qg, const __nv_bfloat16* __restrict__ Kg,
    const __nv_bfloat16* __restrict__ Vg, float* __restrict__ Og,
    int sq, int skv, int nk)
{
    constexpr int PD = 72;                      // smem pitch (bf16 elems)
    __shared__ __align__(16) __nv_bfloat16 Ks[64 * PD];
    __shared__ __align__(16) __nv_bfloat16 Vs[64 * PD];

    const int tid = threadIdx.x;
    const int w = tid >> 5, t = tid & 31;
    const int bh = blockIdx.y;
    const int b = bh >> 4, h = bh & 15;

    const long long qrow0 = (long long)b * 2048 + (long long)blockIdx.x * 128;
    const __nv_bfloat16* Qb = Qg + qrow0 * sq + h * 64;
    const __nv_bfloat16* Kb = Kg + (long long)b * nk * skv + h * 64;
    const __nv_bfloat16* Vb = Vg + (long long)b * nk * skv + h * 64;
    float* Ob = Og + qrow0 * 1024 + h * 64;

    const int qr = w * 32;                      // warp's row base in tile
    const int tr = t >> 2, tc = (t & 3) * 2;    // frag row/col offsets

    // Q fragments (held in registers for the whole kernel)
    uint32_t qa[2][4][4];
#pragma unroll
    for (int mt = 0; mt < 2; mt++) {
        int r0 = qr + mt * 16 + tr;
#pragma unroll
        for (int kc = 0; kc < 4; kc++) {
            int c0 = kc * 16 + tc;
            qa[mt][kc][0] = *reinterpret_cast<const uint32_t*>(&Qb[(long long)r0 * sq + c0]);
            qa[mt][kc][1] = *reinterpret_cast<const uint32_t*>(&Qb[(long long)(r0 + 8) * sq + c0]);
            qa[mt][kc][2] = *reinterpret_cast<const uint32_t*>(&Qb[(long long)r0 * sq + c0 + 8]);
            qa[mt][kc][3] = *reinterpret_cast<const uint32_t*>(&Qb[(long long)(r0 + 8) * sq + c0 + 8]);
        }
    }

    float o[2][8][4];
    float mrow[2][2], lrow[2][2];
#pragma unroll
    for (int mt = 0; mt < 2; mt++) {
        mrow[mt][0] = mrow[mt][1] = -1e30f;
        lrow[mt][0] = lrow[mt][1] = 0.f;
#pragma unroll
        for (int nb = 0; nb < 8; nb++)
#pragma unroll
            for (int e = 0; e < 4; e++) o[mt][nb][e] = 0.f;
    }

    const float CSC = 0.18033688011112042f;     // (1/8) * log2(e)
    const int niter = nk >> 6;

    // ldmatrix lane-address precompute
    const int grp = t >> 3, lrow8 = t & 7;

    for (int kb = 0; kb < niter; kb++) {
        __syncthreads();
        // load K/V tiles (64 x 64 bf16) coalesced, 16B chunks
#pragma unroll
        for (int i = tid; i < 64 * 8; i += 128) {
            int r = i >> 3, c = i & 7;
            long long g = (long long)(kb * 64 + r) * skv + c * 8;
            *reinterpret_cast<uint4*>(&Ks[r * PD + c * 8]) =
                *reinterpret_cast<const uint4*>(&Kb[g]);
            *reinterpret_cast<uint4*>(&Vs[r * PD + c * 8]) =
                *reinterpret_cast<const uint4*>(&Vb[g]);
        }
        __syncthreads();

        // ---- S = Q @ K^T  (raw, scale applied in softmax) ----
        float s[2][8][4];
#pragma unroll
        for (int mt = 0; mt < 2; mt++)
#pragma unroll
            for (int nb = 0; nb < 8; nb++)
#pragma unroll
                for (int e = 0; e < 4; e++) s[mt][nb][e] = 0.f;

#pragma unroll
        for (int kc = 0; kc < 4; kc++) {
#pragma unroll
            for (int nbp = 0; nbp < 4; nbp++) {
                uint32_t r0, r1, r2, r3;
                // tiles: keys nbp*16 + (grp&2)*4 + lrow8 ; d = kc*16 + (grp&1)*8
                const __nv_bfloat16* p =
                    &Ks[(nbp * 16 + (grp & 2) * 4 + lrow8) * PD + kc * 16 + (grp & 1) * 8];
                ldsm4(r0, r1, r2, r3, p);
#pragma unroll
                for (int mt = 0; mt < 2; mt++) {
                    mma16816(s[mt][2 * nbp],     qa[mt][kc][0], qa[mt][kc][1],
                             qa[mt][kc][2], qa[mt][kc][3], r0, r1);
                    mma16816(s[mt][2 * nbp + 1], qa[mt][kc][0], qa[mt][kc][1],
                             qa[mt][kc][2], qa[mt][kc][3], r2, r3);
                }
            }
        }

        // ---- online softmax ----
#pragma unroll
        for (int mt = 0; mt < 2; mt++) {
#pragma unroll
            for (int half = 0; half < 2; half++) {
                int e0 = 2 * half;
                float mx = -1e30f;
#pragma unroll
                for (int nb = 0; nb < 8; nb++)
                    mx = fmaxf(mx, fmaxf(s[mt][nb][e0], s[mt][nb][e0 + 1]));
                mx = fmaxf(mx, __shfl_xor_sync(0xffffffffu, mx, 1));
                mx = fmaxf(mx, __shfl_xor_sync(0xffffffffu, mx, 2));
                float newm = fmaxf(mrow[mt][half], mx);
                float alpha = exp2f((mrow[mt][half] - newm) * CSC);
                float sum = 0.f;
#pragma unroll
                for (int nb = 0; nb < 8; nb++) {
                    float p0 = exp2f((s[mt][nb][e0] - newm) * CSC);
                    float p1 = exp2f((s[mt][nb][e0 + 1] - newm) * CSC);
                    s[mt][nb][e0] = p0; s[mt][nb][e0 + 1] = p1;
                    sum += p0 + p1;
                }
                sum += __shfl_xor_sync(0xffffffffu, sum, 1);
                sum += __shfl_xor_sync(0xffffffffu, sum, 2);
                lrow[mt][half] = lrow[mt][half] * alpha + sum;
                mrow[mt][half] = newm;
#pragma unroll
                for (int nb = 0; nb < 8; nb++) {
                    o[mt][nb][e0]     *= alpha;
                    o[mt][nb][e0 + 1] *= alpha;
                }
            }
        }

        // ---- O += P @ V ----
#pragma unroll
        for (int kcP = 0; kcP < 4; kcP++) {
            uint32_t pa[2][4];
#pragma unroll
            for (int mt = 0; mt < 2; mt++) {
                pa[mt][0] = packbf2(s[mt][2 * kcP][0],     s[mt][2 * kcP][1]);
                pa[mt][1] = packbf2(s[mt][2 * kcP][2],     s[mt][2 * kcP][3]);
                pa[mt][2] = packbf2(s[mt][2 * kcP + 1][0], s[mt][2 * kcP + 1][1]);
                pa[mt][3] = packbf2(s[mt][2 * kcP + 1][2], s[mt][2 * kcP + 1][3]);
            }
#pragma unroll
            for (int nbp = 0; nbp < 4; nbp++) {
                uint32_t r0, r1, r2, r3;
                // tiles: keys kcP*16 + (grp&1)*8 + lrow8 ; d = nbp*16 + (grp&2)*4
                const __nv_bfloat16* p =
                    &Vs[(kcP * 16 + (grp & 1) * 8 + lrow8) * PD + nbp * 16 + (grp & 2) * 4];
                ldsm4t(r0, r1, r2, r3, p);
#pragma unroll
                for (int mt = 0; mt < 2; mt++) {
                    mma16816(o[mt][2 * nbp],     pa[mt][0], pa[mt][1], pa[mt][2], pa[mt][3], r0, r1);
                    mma16816(o[mt][2 * nbp + 1], pa[mt][0], pa[mt][1], pa[mt][2], pa[mt][3], r2, r3);
                }
            }
        }
    }

    // ---- normalize + write ----
#pragma unroll
    for (int mt = 0; mt < 2; mt++) {
        int r0 = qr + mt * 16 + tr;
        float inv0 = 1.0f / lrow[mt][0];
        float inv1 = 1.0f / lrow[mt][1];
#pragma unroll
        for (int nb = 0; nb < 8; nb++) {
            int col = nb * 8 + tc;
            float2 v0 = make_float2(o[mt][nb][0] * inv0, o[mt][nb][1] * inv0);
            float2 v1 = make_float2(o[mt][nb][2] * inv1, o[mt][nb][3] * inv1);
            *reinterpret_cast<float2*>(&Ob[(long long)r0 * 1024 + col])       = v0;
            *reinterpret_cast<float2*>(&Ob[(long long)(r0 + 8) * 1024 + col]) = v1;
        }
    }
}

// ---------------- dense tf32 GEMM 128x128x16 with fused epilogue ----------------
// C = act(A @ B + bias) [+ res], A:[M,K] lda=K, B:[K,N] ldb=N.
template <bool GELU, bool RES, bool OBF16>
__global__ __launch_bounds__(256) void gemm128(
    const float* __restrict__ A, const float* __restrict__ Bm,
    const float* __restrict__ bias, const float* __restrict__ res,
    void* __restrict__ Cout, int K, int N)
{
    constexpr int BM = 128, BN = 128, BK = 16;
    constexpr int AP = BK + 4, BP = BN + 4;
    constexpr int ASZ = BM * AP, BSZ = BK * BP;
    constexpr int PIPE = 2 * ASZ + 2 * BSZ;      // 9344 floats
    constexpr int STG  = 64 * 132;               // 8448 floats
    __shared__ __align__(16) float smem[PIPE > STG ? PIPE : STG];
    float* As[2] = { smem, smem + ASZ };
    float* Bs[2] = { smem + 2 * ASZ, smem + 2 * ASZ + BSZ };

    const int tid = threadIdx.x;
    const float* Ab = A + (long long)blockIdx.y * BM * K;
    const float* Bb = Bm + (long long)blockIdx.x * BN;

    float4 ra[2], rb[2];
    auto ldgA = [&](int kt) {
#pragma unroll
        for (int i = 0; i < 2; i++) {
            int idx = tid + i * 256;
            int row = idx >> 2, c4 = idx & 3;
            ra[i] = *reinterpret_cast<const float4*>(Ab + (long long)row * K + kt * BK + c4 * 4);
        }
    };
    auto ldgB = [&](int kt) {
#pragma unroll
        for (int i = 0; i < 2; i++) {
            int idx = tid + i * 256;
            int row = idx >> 5, c4 = idx & 31;
            rb[i] = *reinterpret_cast<const float4*>(Bb + (long long)(kt * BK + row) * N + c4 * 4);
        }
    };
    auto stsA = [&](int buf) {
#pragma unroll
        for (int i = 0; i < 2; i++) {
            int idx = tid + i * 256;
            int row = idx >> 2, c4 = idx & 3;
            float* p = &As[buf][row * AP + c4 * 4];
            p[0] = wmma::__float_to_tf32(ra[i].x);
            p[1] = wmma::__float_to_tf32(ra[i].y);
            p[2] = wmma::__float_to_tf32(ra[i].z);
            p[3] = wmma::__float_to_tf32(ra[i].w);
        }
    };
    auto stsB = [&](int buf) {
#pragma unroll
        for (int i = 0; i < 2; i++) {
            int idx = tid + i * 256;
            int row = idx >> 5, c4 = idx & 31;
            float* p = &Bs[buf][row * BP + c4 * 4];
            p[0] = wmma::__float_to_tf32(rb[i].x);
            p[1] = wmma::__float_to_tf32(rb[i].y);
            p[2] = wmma::__float_to_tf32(rb[i].z);
            p[3] = wmma::__float_to_tf32(rb[i].w);
        }
    };

    const int w = tid >> 5;
    const int wr = w >> 2, wc = w & 3;           // 2x4 warps, 64x32 per warp
    const int rbase = wr * 64, cbase = wc * 32;

    wmma::fragment<wmma::accumulator, 16, 16, 8, float> acc[4][2];
#pragma unroll
    for (int i = 0; i < 4; i++)
#pragma unroll
        for (int j = 0; j < 2; j++) wmma::fill_fragment(acc[i][j], 0.0f);

    const int KT = K / BK;
    ldgA(0); ldgB(0); stsA(0); stsB(0);
    __syncthreads();

    for (int kt = 0; kt < KT; kt++) {
        const int cur = kt & 1;
        if (kt + 1 < KT) { ldgA(kt + 1); ldgB(kt + 1); }
#pragma unroll
        for (int kk = 0; kk < BK; kk += 8) {
            wmma::fragment<wmma::matrix_a, 16, 16, 8, wmma::precision::tf32, wmma::row_major> af[4];
#pragma unroll
            for (int i = 0; i < 4; i++)
                wmma::load_matrix_sync(af[i], &As[cur][(rbase + i * 16) * AP + kk], AP);
#pragma unroll
            for (int j = 0; j < 2; j++) {
                wmma::fragment<wmma::matrix_b, 16, 16, 8, wmma::precision::tf32, wmma::row_major> bf;
                wmma::load_matrix_sync(bf, &Bs[cur][kk * BP + cbase + j * 16], BP);
#pragma unroll
                for (int i = 0; i < 4; i++) wmma::mma_sync(acc[i][j], af[i], bf, acc[i][j]);
            }
        }
        if (kt + 1 < KT) { stsA((kt + 1) & 1); stsB((kt + 1) & 1); }
        __syncthreads();
    }

    // ---- fused epilogue via smem staging (two 64-row halves) ----
    float* stage = smem;
    const int gr_base = blockIdx.y * BM;
    const int gc_base = blockIdx.x * BN;
#pragma unroll 1
    for (int half = 0; half < 2; half++) {
        if (wr == half) {
#pragma unroll
            for (int i = 0; i < 4; i++)
#pragma unroll
                for (int j = 0; j < 2; j++)
                    wmma::store_matrix_sync(&stage[(i * 16) * 132 + cbase + j * 16],
                                            acc[i][j], 132, wmma::mem_row_major);
        }
        __syncthreads();
#pragma unroll
        for (int i = 0; i < 8; i++) {
            int idx = tid + i * 256;
            int row = idx >> 5, c4 = (idx & 31) * 4;
            float4 v = *reinterpret_cast<float4*>(&stage[row * 132 + c4]);
            int gr = gr_base + half * 64 + row;
            int gc = gc_base + c4;
            v.x += bias[gc]; v.y += bias[gc + 1]; v.z += bias[gc + 2]; v.w += bias[gc + 3];
            if (GELU) {
                float* pv = reinterpret_cast<float*>(&v);
#pragma unroll
                for (int e = 0; e < 4; e++) {
                    float xx = pv[e];
                    float tt = 0.7978845608028654f * (xx + 0.044715f * xx * xx * xx);
                    pv[e] = 0.5f * xx * (1.0f + tanhf(tt));
                }
            }
            if (RES) {
                float4 r4 = *reinterpret_cast<const float4*>(&res[(long long)gr * N + gc]);
                v.x += r4.x; v.y += r4.y; v.z += r4.z; v.w += r4.w;
            }
            if (OBF16) {
                uint2 u;
                u.x = packbf2(v.x, v.y);
                u.y = packbf2(v.z, v.w);
                *reinterpret_cast<uint2*>(
                    &reinterpret_cast<__nv_bfloat16*>(Cout)[(long long)gr * N + gc]) = u;
            } else {
                *reinterpret_cast<float4*>(
                    &reinterpret_cast<float*>(Cout)[(long long)gr * N + gc]) = v;
            }
        }
        __syncthreads();
    }
}

// ---------------- host ----------------
static void* devptr(const void* symbol)
{
    void* p = nullptr;
    cudaGetSymbolAddress(&p, symbol);
    return p;
}

extern "C" void kernel_launch(void* const* d_in, const int* in_sizes, int n_in,
                              void* d_out, int out_size)
{
    const float* x    = (const float*)d_in[0];
    const float* ctx  = (const float*)d_in[1];
    const float* Wqkv = (const float*)d_in[2];
    const float* bqkv = (const float*)d_in[3];
    const float* Wos  = (const float*)d_in[4];
    const float* bos  = (const float*)d_in[5];
    const float* Wq   = (const float*)d_in[6];
    const float* bq   = (const float*)d_in[7];
    const float* Wkv  = (const float*)d_in[8];
    const float* bkv  = (const float*)d_in[9];
    const float* Woc  = (const float*)d_in[10];
    const float* boc  = (const float*)d_in[11];
    const float* W1   = (const float*)d_in[12];
    const float* b1   = (const float*)d_in[13];
    const float* W2   = (const float*)d_in[14];
    const float* b2   = (const float*)d_in[15];
    float* out = (float*)d_out;

    float*         ln   = (float*)devptr(g_ln);
    __nv_bfloat16* qkv  = (__nv_bfloat16*)devptr(g_qkv);
    __nv_bfloat16* q    = (__nv_bfloat16*)devptr(g_q);
    __nv_bfloat16* kv   = (__nv_bfloat16*)devptr(g_kv);
    float*         attn = (float*)devptr(g_attn);
    float*         x1   = (float*)devptr(g_x1);
    float*         x2   = (float*)devptr(g_x2);
    float*         mid  = (float*)devptr(g_mid);

    // ---- self-attention ----
    ln_kernel<<<4096, 256>>>(x, ln, 1024);
    gemm128<false, false, true><<<dim3(3072 / 128, 4096 / 128), 256>>>(
        ln, Wqkv, bqkv, nullptr, qkv, 1024, 3072);
    flash_kernel<<<dim3(16, 32), 128>>>(qkv, qkv + 1024, qkv + 2048, attn,
                                        3072, 3072, 2048);
    gemm128<false, true, false><<<dim3(1024 / 128, 4096 / 128), 256>>>(
        attn, Wos, bos, x, x1, 1024, 1024);

    // ---- cross-attention ----
    ln_kernel<<<4096, 256>>>(x1, ln, 1024);
    gemm128<false, false, true><<<dim3(1024 / 128, 4096 / 128), 256>>>(
        ln, Wq, bq, nullptr, q, 1024, 1024);
    gemm128<false, false, true><<<dim3(2048 / 128, 2048 / 128), 256>>>(
        ctx, Wkv, bkv, nullptr, kv, 1024, 2048);
    flash_kernel<<<dim3(16, 32), 128>>>(q, kv, kv + 1024, attn,
                                        1024, 2048, 1024);
    gemm128<false, true, false><<<dim3(1024 / 128, 4096 / 128), 256>>>(
        attn, Woc, boc, x1, x2, 1024, 1024);

    // ---- MLP ----
    ln_kernel<<<4096, 256>>>(x2, ln, 1024);
    gemm128<true, false, false><<<dim3(4096 / 128, 4096 / 128), 256>>>(
        ln, W1, b1, nullptr, mid, 1024, 4096);
    gemm128<false, true, false><<<dim3(1024 / 128, 4096 / 128), 256>>>(
        mid, W2, b2, x2, out, 4096, 1024);
}

// round 5
// speedup vs baseline: 1.8755x; 1.3203x over previous
#include <cuda_runtime.h>
#include <cuda_bf16.h>
#include <mma.h>
#include <cstdint>

using namespace nvcuda;

// Dims: B=2, N=2048, M=1024, C=1024, H=16, D=64, HID=4096
// TQ = 4096 tokens (B*N), TKV = 2048 (B*M)

// ---------------- scratch ----------------
__device__ float          g_ln  [4096u * 1024u];
__device__ __nv_bfloat16  g_qkv [4096u * 3072u];   // bf16 q|k|v
__device__ __nv_bfloat16  g_q   [4096u * 1024u];   // bf16 cross q
__device__ __nv_bfloat16  g_kv  [2048u * 2048u];   // bf16 cross k|v
__device__ float          g_attn[4096u * 1024u];
__device__ float          g_x1  [4096u * 1024u];
__device__ float          g_x2  [4096u * 1024u];
__device__ float          g_mid [4096u * 4096u];

// ---------------- helpers ----------------
__device__ __forceinline__ uint32_t smem_u32(const void* p)
{
    uint32_t a;
    asm("{ .reg .u64 t; cvta.to.shared.u64 t, %1; cvt.u32.u64 %0, t; }" : "=r"(a) : "l"(p));
    return a;
}
__device__ __forceinline__ uint32_t packbf2(float lo, float hi)
{
    __nv_bfloat162 h = __floats2bfloat162_rn(lo, hi);
    return *reinterpret_cast<uint32_t*>(&h);
}
__device__ __forceinline__ void cp16(uint32_t s, const void* g)
{
    asm volatile("cp.async.cg.shared.global [%0], [%1], 16;" :: "r"(s), "l"(g));
}
__device__ __forceinline__ void cp_commit() { asm volatile("cp.async.commit_group;"); }

// ---------------- LayerNorm ----------------
__global__ __launch_bounds__(256) void ln_kernel(const float* __restrict__ x,
                                                 float* __restrict__ out, int cols)
{
    long long base = (long long)blockIdx.x * cols;
    float s = 0.f, ss = 0.f;
    for (int i = threadIdx.x; i < cols; i += 256) {
        float v = x[base + i];
        s += v; ss += v * v;
    }
    __shared__ float shs[32], shq[32];
    for (int o = 16; o; o >>= 1) {
        s  += __shfl_xor_sync(0xffffffffu, s,  o);
        ss += __shfl_xor_sync(0xffffffffu, ss, o);
    }
    int w = threadIdx.x >> 5, l = threadIdx.x & 31;
    if (l == 0) { shs[w] = s; shq[w] = ss; }
    __syncthreads();
    if (w == 0) {
        float a = (l < 8) ? shs[l] : 0.f;
        float b = (l < 8) ? shq[l] : 0.f;
        for (int o = 4; o; o >>= 1) {
            a += __shfl_xor_sync(0xffffffffu, a, o);
            b += __shfl_xor_sync(0xffffffffu, b, o);
        }
        if (l == 0) { shs[0] = a; shq[0] = b; }
    }
    __syncthreads();
    float mean = shs[0] * (1.0f / cols);
    float var  = shq[0] * (1.0f / cols) - mean * mean;
    float inv  = rsqrtf(var + 1e-6f);
    for (int i = threadIdx.x; i < cols; i += 256)
        out[base + i] = (x[base + i] - mean) * inv;
}

// ---------------- mma / ldmatrix helpers (flash) ----------------
__device__ __forceinline__ void mma16816(float c[4], uint32_t a0, uint32_t a1,
                                         uint32_t a2, uint32_t a3,
                                         uint32_t b0, uint32_t b1)
{
    asm volatile("mma.sync.aligned.m16n8k16.row.col.f32.bf16.bf16.f32 "
                 "{%0,%1,%2,%3}, {%4,%5,%6,%7}, {%8,%9}, {%0,%1,%2,%3};"
                 : "+f"(c[0]), "+f"(c[1]), "+f"(c[2]), "+f"(c[3])
                 : "r"(a0), "r"(a1), "r"(a2), "r"(a3), "r"(b0), "r"(b1));
}
__device__ __forceinline__ void ldsm4(uint32_t& r0, uint32_t& r1, uint32_t& r2,
                                      uint32_t& r3, const void* p)
{
    uint32_t a = smem_u32(p);
    asm volatile("ldmatrix.sync.aligned.m8n8.x4.shared.b16 {%0,%1,%2,%3}, [%4];"
                 : "=r"(r0), "=r"(r1), "=r"(r2), "=r"(r3) : "r"(a));
}
__device__ __forceinline__ void ldsm4t(uint32_t& r0, uint32_t& r1, uint32_t& r2,
                                       uint32_t& r3, const void* p)
{
    uint32_t a = smem_u32(p);
    asm volatile("ldmatrix.sync.aligned.m8n8.x4.trans.shared.b16 {%0,%1,%2,%3}, [%4];"
                 : "=r"(r0), "=r"(r1), "=r"(r2), "=r"(r3) : "r"(a));
}

// ---------------- fused flash attention (bf16, FA2 layout) ----------------
__global__ __launch_bounds__(128) void flash_kernel(
    const __nv_bfloat16* __restrict__ Qg, const __nv_bfloat16* __restrict__ Kg,
    const __nv_bfloat16* __restrict__ Vg, float* __restrict__ Og,
    int sq, int skv, int nk)
{
    constexpr int PD = 72;
    __shared__ __align__(16) __nv_bfloat16 Ks[64 * PD];
    __shared__ __align__(16) __nv_bfloat16 Vs[64 * PD];

    const int tid = threadIdx.x;
    const int w = tid >> 5, t = tid & 31;
    const int bh = blockIdx.y;
    const int b = bh >> 4, h = bh & 15;

    const long long qrow0 = (long long)b * 2048 + (long long)blockIdx.x * 128;
    const __nv_bfloat16* Qb = Qg + qrow0 * sq + h * 64;
    const __nv_bfloat16* Kb = Kg + (long long)b * nk * skv + h * 64;
    const __nv_bfloat16* Vb = Vg + (long long)b * nk * skv + h * 64;
    float* Ob = Og + qrow0 * 1024 + h * 64;

    const int qr = w * 32;
    const int tr = t >> 2, tc = (t & 3) * 2;

    uint32_t qa[2][4][4];
#pragma unroll
    for (int mt = 0; mt < 2; mt++) {
        int r0 = qr + mt * 16 + tr;
#pragma unroll
        for (int kc = 0; kc < 4; kc++) {
            int c0 = kc * 16 + tc;
            qa[mt][kc][0] = *reinterpret_cast<const uint32_t*>(&Qb[(long long)r0 * sq + c0]);
            qa[mt][kc][1] = *reinterpret_cast<const uint32_t*>(&Qb[(long long)(r0 + 8) * sq + c0]);
            qa[mt][kc][2] = *reinterpret_cast<const uint32_t*>(&Qb[(long long)r0 * sq + c0 + 8]);
            qa[mt][kc][3] = *reinterpret_cast<const uint32_t*>(&Qb[(long long)(r0 + 8) * sq + c0 + 8]);
        }
    }

    float o[2][8][4];
    float mrow[2][2], lrow[2][2];
#pragma unroll
    for (int mt = 0; mt < 2; mt++) {
        mrow[mt][0] = mrow[mt][1] = -1e30f;
        lrow[mt][0] = lrow[mt][1] = 0.f;
#pragma unroll
        for (int nb = 0; nb < 8; nb++)
#pragma unroll
            for (int e = 0; e < 4; e++) o[mt][nb][e] = 0.f;
    }

    const float CSC = 0.18033688011112042f;     // (1/8)*log2(e)
    const int niter = nk >> 6;
    const int grp = t >> 3, lrow8 = t & 7;

    for (int kb = 0; kb < niter; kb++) {
        __syncthreads();
#pragma unroll
        for (int i = tid; i < 64 * 8; i += 128) {
            int r = i >> 3, c = i & 7;
            long long g = (long long)(kb * 64 + r) * skv + c * 8;
            *reinterpret_cast<uint4*>(&Ks[r * PD + c * 8]) =
                *reinterpret_cast<const uint4*>(&Kb[g]);
            *reinterpret_cast<uint4*>(&Vs[r * PD + c * 8]) =
                *reinterpret_cast<const uint4*>(&Vb[g]);
        }
        __syncthreads();

        float s[2][8][4];
#pragma unroll
        for (int mt = 0; mt < 2; mt++)
#pragma unroll
            for (int nb = 0; nb < 8; nb++)
#pragma unroll
                for (int e = 0; e < 4; e++) s[mt][nb][e] = 0.f;

#pragma unroll
        for (int kc = 0; kc < 4; kc++) {
#pragma unroll
            for (int nbp = 0; nbp < 4; nbp++) {
                uint32_t r0, r1, r2, r3;
                const __nv_bfloat16* p =
                    &Ks[(nbp * 16 + (grp & 2) * 4 + lrow8) * PD + kc * 16 + (grp & 1) * 8];
                ldsm4(r0, r1, r2, r3, p);
#pragma unroll
                for (int mt = 0; mt < 2; mt++) {
                    mma16816(s[mt][2 * nbp],     qa[mt][kc][0], qa[mt][kc][1],
                             qa[mt][kc][2], qa[mt][kc][3], r0, r1);
                    mma16816(s[mt][2 * nbp + 1], qa[mt][kc][0], qa[mt][kc][1],
                             qa[mt][kc][2], qa[mt][kc][3], r2, r3);
                }
            }
        }

#pragma unroll
        for (int mt = 0; mt < 2; mt++) {
#pragma unroll
            for (int half = 0; half < 2; half++) {
                int e0 = 2 * half;
                float mx = -1e30f;
#pragma unroll
                for (int nb = 0; nb < 8; nb++)
                    mx = fmaxf(mx, fmaxf(s[mt][nb][e0], s[mt][nb][e0 + 1]));
                mx = fmaxf(mx, __shfl_xor_sync(0xffffffffu, mx, 1));
                mx = fmaxf(mx, __shfl_xor_sync(0xffffffffu, mx, 2));
                float newm = fmaxf(mrow[mt][half], mx);
                float alpha = exp2f((mrow[mt][half] - newm) * CSC);
                float sum = 0.f;
#pragma unroll
                for (int nb = 0; nb < 8; nb++) {
                    float p0 = exp2f((s[mt][nb][e0] - newm) * CSC);
                    float p1 = exp2f((s[mt][nb][e0 + 1] - newm) * CSC);
                    s[mt][nb][e0] = p0; s[mt][nb][e0 + 1] = p1;
                    sum += p0 + p1;
                }
                sum += __shfl_xor_sync(0xffffffffu, sum, 1);
                sum += __shfl_xor_sync(0xffffffffu, sum, 2);
                lrow[mt][half] = lrow[mt][half] * alpha + sum;
                mrow[mt][half] = newm;
#pragma unroll
                for (int nb = 0; nb < 8; nb++) {
                    o[mt][nb][e0]     *= alpha;
                    o[mt][nb][e0 + 1] *= alpha;
                }
            }
        }

#pragma unroll
        for (int kcP = 0; kcP < 4; kcP++) {
            uint32_t pa[2][4];
#pragma unroll
            for (int mt = 0; mt < 2; mt++) {
                pa[mt][0] = packbf2(s[mt][2 * kcP][0],     s[mt][2 * kcP][1]);
                pa[mt][1] = packbf2(s[mt][2 * kcP][2],     s[mt][2 * kcP][3]);
                pa[mt][2] = packbf2(s[mt][2 * kcP + 1][0], s[mt][2 * kcP + 1][1]);
                pa[mt][3] = packbf2(s[mt][2 * kcP + 1][2], s[mt][2 * kcP + 1][3]);
            }
#pragma unroll
            for (int nbp = 0; nbp < 4; nbp++) {
                uint32_t r0, r1, r2, r3;
                const __nv_bfloat16* p =
                    &Vs[(kcP * 16 + (grp & 1) * 8 + lrow8) * PD + nbp * 16 + (grp & 2) * 4];
                ldsm4t(r0, r1, r2, r3, p);
#pragma unroll
                for (int mt = 0; mt < 2; mt++) {
                    mma16816(o[mt][2 * nbp],     pa[mt][0], pa[mt][1], pa[mt][2], pa[mt][3], r0, r1);
                    mma16816(o[mt][2 * nbp + 1], pa[mt][0], pa[mt][1], pa[mt][2], pa[mt][3], r2, r3);
                }
            }
        }
    }

#pragma unroll
    for (int mt = 0; mt < 2; mt++) {
        int r0 = qr + mt * 16 + tr;
        float inv0 = 1.0f / lrow[mt][0];
        float inv1 = 1.0f / lrow[mt][1];
#pragma unroll
        for (int nb = 0; nb < 8; nb++) {
            int col = nb * 8 + tc;
            float2 v0 = make_float2(o[mt][nb][0] * inv0, o[mt][nb][1] * inv0);
            float2 v1 = make_float2(o[mt][nb][2] * inv1, o[mt][nb][3] * inv1);
            *reinterpret_cast<float2*>(&Ob[(long long)r0 * 1024 + col])       = v0;
            *reinterpret_cast<float2*>(&Ob[(long long)(r0 + 8) * 1024 + col]) = v1;
        }
    }
}

// ---------------- tf32 GEMM, cp.async 3-stage, BK=32, 2 CTAs/SM ----------------
// C = act(A @ B + bias) [+ res], A:[M,K] lda=K, B:[K,N] ldb=N. tf32 via truncation.
template <bool GELU, bool RES, bool OBF16>
__global__ __launch_bounds__(256, 2) void gemm_cp(
    const float* __restrict__ A, const float* __restrict__ Bm,
    const float* __restrict__ bias, const float* __restrict__ res,
    void* __restrict__ Cout, int K, int N)
{
    constexpr int BM = 128, BN = 128, BK = 32;
    constexpr int AP = BK + 4;          // 36
    constexpr int BP = BN + 4;          // 132
    constexpr int ASZ = BM * AP;        // 4608
    constexpr int BSZ = BK * BP;        // 4224
    constexpr int SSZ = ASZ + BSZ;      // 8832 floats / stage
    extern __shared__ __align__(16) float smem[];

    const int tid = threadIdx.x;
    const float* Ab = A + (long long)blockIdx.y * BM * K;
    const float* Bb = Bm + blockIdx.x * BN;

    auto load_stage = [&](int kt, int s) {
        float* As = smem + s * SSZ;
        float* Bs = As + ASZ;
#pragma unroll
        for (int i = 0; i < 4; i++) {
            int idx = tid + i * 256;
            int row = idx >> 3, c = idx & 7;
            cp16(smem_u32(&As[row * AP + c * 4]),
                 Ab + (long long)row * K + kt * BK + c * 4);
        }
#pragma unroll
        for (int i = 0; i < 4; i++) {
            int idx = tid + i * 256;
            int row = idx >> 5, c = idx & 31;
            cp16(smem_u32(&Bs[row * BP + c * 4]),
                 Bb + (long long)(kt * BK + row) * N + c * 4);
        }
        cp_commit();
    };

    const int w = tid >> 5;
    const int wr = w >> 2, wc = w & 3;       // 2x4 warps, 64x32 each
    const int rbase = wr * 64, cbase = wc * 32;

    wmma::fragment<wmma::accumulator, 16, 16, 8, float> acc[4][2];
#pragma unroll
    for (int i = 0; i < 4; i++)
#pragma unroll
        for (int j = 0; j < 2; j++) wmma::fill_fragment(acc[i][j], 0.0f);

    const int KT = K / BK;
    load_stage(0, 0);
    load_stage(1, 1);

    for (int kt = 0; kt < KT; kt++) {
        if (kt + 1 < KT) asm volatile("cp.async.wait_group 1;" ::: "memory");
        else             asm volatile("cp.async.wait_group 0;" ::: "memory");
        __syncthreads();
        if (kt + 2 < KT) load_stage(kt + 2, (kt + 2) % 3);

        const float* As = smem + (kt % 3) * SSZ;
        const float* Bs = As + ASZ;
#pragma unroll
        for (int kk = 0; kk < BK; kk += 8) {
            wmma::fragment<wmma::matrix_a, 16, 16, 8, wmma::precision::tf32, wmma::row_major> af[4];
#pragma unroll
            for (int i = 0; i < 4; i++)
                wmma::load_matrix_sync(af[i], &As[(rbase + i * 16) * AP + kk], AP);
#pragma unroll
            for (int j = 0; j < 2; j++) {
                wmma::fragment<wmma::matrix_b, 16, 16, 8, wmma::precision::tf32, wmma::row_major> bf;
                wmma::load_matrix_sync(bf, &Bs[kk * BP + cbase + j * 16], BP);
#pragma unroll
                for (int i = 0; i < 4; i++) wmma::mma_sync(acc[i][j], af[i], bf, acc[i][j]);
            }
        }
    }
    __syncthreads();

    // ---- fused epilogue via smem staging (two 64-row halves) ----
    float* stage = smem;
    const int gr_base = blockIdx.y * BM;
    const int gc_base = blockIdx.x * BN;
#pragma unroll 1
    for (int half = 0; half < 2; half++) {
        if (wr == half) {
#pragma unroll
            for (int i = 0; i < 4; i++)
#pragma unroll
                for (int j = 0; j < 2; j++)
                    wmma::store_matrix_sync(&stage[(i * 16) * 132 + cbase + j * 16],
                                            acc[i][j], 132, wmma::mem_row_major);
        }
        __syncthreads();
#pragma unroll
        for (int i = 0; i < 8; i++) {
            int idx = tid + i * 256;
            int row = idx >> 5, c4 = (idx & 31) * 4;
            float4 v = *reinterpret_cast<float4*>(&stage[row * 132 + c4]);
            int gr = gr_base + half * 64 + row;
            int gc = gc_base + c4;
            v.x += bias[gc]; v.y += bias[gc + 1]; v.z += bias[gc + 2]; v.w += bias[gc + 3];
            if (GELU) {
                float* pv = reinterpret_cast<float*>(&v);
#pragma unroll
                for (int e = 0; e < 4; e++) {
                    float xx = pv[e];
                    float tt = 0.7978845608028654f * (xx + 0.044715f * xx * xx * xx);
                    pv[e] = 0.5f * xx * (1.0f + tanhf(tt));
                }
            }
            if (RES) {
                float4 r4 = *reinterpret_cast<const float4*>(&res[(long long)gr * N + gc]);
                v.x += r4.x; v.y += r4.y; v.z += r4.z; v.w += r4.w;
            }
            if (OBF16) {
                uint2 u;
                u.x = packbf2(v.x, v.y);
                u.y = packbf2(v.z, v.w);
                *reinterpret_cast<uint2*>(
                    &reinterpret_cast<__nv_bfloat16*>(Cout)[(long long)gr * N + gc]) = u;
            } else {
                *reinterpret_cast<float4*>(
                    &reinterpret_cast<float*>(Cout)[(long long)gr * N + gc]) = v;
            }
        }
        __syncthreads();
    }
}

// ---------------- host ----------------
static void* devptr(const void* symbol)
{
    void* p = nullptr;
    cudaGetSymbolAddress(&p, symbol);
    return p;
}

extern "C" void kernel_launch(void* const* d_in, const int* in_sizes, int n_in,
                              void* d_out, int out_size)
{
    const float* x    = (const float*)d_in[0];
    const float* ctx  = (const float*)d_in[1];
    const float* Wqkv = (const float*)d_in[2];
    const float* bqkv = (const float*)d_in[3];
    const float* Wos  = (const float*)d_in[4];
    const float* bos  = (const float*)d_in[5];
    const float* Wq   = (const float*)d_in[6];
    const float* bq   = (const float*)d_in[7];
    const float* Wkv  = (const float*)d_in[8];
    const float* bkv  = (const float*)d_in[9];
    const float* Woc  = (const float*)d_in[10];
    const float* boc  = (const float*)d_in[11];
    const float* W1   = (const float*)d_in[12];
    const float* b1   = (const float*)d_in[13];
    const float* W2   = (const float*)d_in[14];
    const float* b2   = (const float*)d_in[15];
    float* out = (float*)d_out;

    float*         ln   = (float*)devptr(g_ln);
    __nv_bfloat16* qkv  = (__nv_bfloat16*)devptr(g_qkv);
    __nv_bfloat16* q    = (__nv_bfloat16*)devptr(g_q);
    __nv_bfloat16* kv   = (__nv_bfloat16*)devptr(g_kv);
    float*         attn = (float*)devptr(g_attn);
    float*         x1   = (float*)devptr(g_x1);
    float*         x2   = (float*)devptr(g_x2);
    float*         mid  = (float*)devptr(g_mid);

    const int SMEM = 3 * 8832 * 4;   // 105984 bytes
    static int s_init = 0;
    if (!s_init) {
        s_init = 1;
        cudaFuncSetAttribute(gemm_cp<false, false, true>,
                             cudaFuncAttributeMaxDynamicSharedMemorySize, SMEM);
        cudaFuncSetAttribute(gemm_cp<false, true, false>,
                             cudaFuncAttributeMaxDynamicSharedMemorySize, SMEM);
        cudaFuncSetAttribute(gemm_cp<true, false, false>,
                             cudaFuncAttributeMaxDynamicSharedMemorySize, SMEM);
    }

    // ---- self-attention ----
    ln_kernel<<<4096, 256>>>(x, ln, 1024);
    gemm_cp<false, false, true><<<dim3(24, 32), 256, SMEM>>>(
        ln, Wqkv, bqkv, nullptr, qkv, 1024, 3072);
    flash_kernel<<<dim3(16, 32), 128>>>(qkv, qkv + 1024, qkv + 2048, attn,
                                        3072, 3072, 2048);
    gemm_cp<false, true, false><<<dim3(8, 32), 256, SMEM>>>(
        attn, Wos, bos, x, x1, 1024, 1024);

    // ---- cross-attention ----
    ln_kernel<<<4096, 256>>>(x1, ln, 1024);
    gemm_cp<false, false, true><<<dim3(8, 32), 256, SMEM>>>(
        ln, Wq, bq, nullptr, q, 1024, 1024);
    gemm_cp<false, false, true><<<dim3(16, 16), 256, SMEM>>>(
        ctx, Wkv, bkv, nullptr, kv, 1024, 2048);
    flash_kernel<<<dim3(16, 32), 128>>>(q, kv, kv + 1024, attn,
                                        1024, 2048, 1024);
    gemm_cp<false, true, false><<<dim3(8, 32), 256, SMEM>>>(
        attn, Woc, boc, x1, x2, 1024, 1024);

    // ---- MLP ----
    ln_kernel<<<4096, 256>>>(x2, ln, 1024);
    gemm_cp<true, false, false><<<dim3(32, 32), 256, SMEM>>>(
        ln, W1, b1, nullptr, mid, 1024, 4096);
    gemm_cp<false, true, false><<<dim3(8, 32), 256, SMEM>>>(
        mid, W2, b2, x2, out, 4096, 1024);
}

// round 6
// speedup vs baseline: 2.5986x; 1.3856x over previous
#include <cuda_runtime.h>
#include <cuda_bf16.h>
#include <cstdint>

// Dims: B=2, N=2048, M=1024, C=1024, H=16, D=64, HID=4096
// TQ = 4096 (B*N), TKV = 2048 (B*M)

// ---------------- scratch ----------------
__device__ __nv_bfloat16 g_w_hi[16777216];
__device__ __nv_bfloat16 g_w_lo[16777216];
__device__ __nv_bfloat16 g_lnh[4096u * 1024u], g_lnl[4096u * 1024u];
__device__ __nv_bfloat16 g_ath[4096u * 1024u], g_atl[4096u * 1024u];
__device__ __nv_bfloat16 g_cxh[2048u * 1024u], g_cxl[2048u * 1024u];
__device__ __nv_bfloat16 g_mdh[4096u * 4096u], g_mdl[4096u * 4096u];
__device__ __nv_bfloat16 g_qkv[4096u * 3072u];
__device__ __nv_bfloat16 g_q  [4096u * 1024u];
__device__ __nv_bfloat16 g_kv [2048u * 2048u];
__device__ float g_x1[4096u * 1024u];
__device__ float g_x2[4096u * 1024u];

// weight offsets (elements)
#define OFF_QKV 0
#define OFF_OS  3145728
#define OFF_Q   4194304
#define OFF_KV  5242880
#define OFF_OC  7340032
#define OFF_W1  8388608
#define OFF_W2  12582912

// ---------------- helpers ----------------
__device__ __forceinline__ uint32_t smem_u32(const void* p)
{
    uint32_t a;
    asm("{ .reg .u64 t; cvta.to.shared.u64 t, %1; cvt.u32.u64 %0, t; }" : "=r"(a) : "l"(p));
    return a;
}
__device__ __forceinline__ uint32_t packbf2(float lo, float hi)
{
    __nv_bfloat162 h = __floats2bfloat162_rn(lo, hi);
    return *reinterpret_cast<uint32_t*>(&h);
}
__device__ __forceinline__ void split_hilo(float v, __nv_bfloat16& h, __nv_bfloat16& l)
{
    h = __float2bfloat16(v);
    l = __float2bfloat16(v - __bfloat162float(h));
}
__device__ __forceinline__ void cp16(uint32_t s, const void* g)
{
    asm volatile("cp.async.cg.shared.global [%0], [%1], 16;" :: "r"(s), "l"(g));
}
__device__ __forceinline__ void cp_commit() { asm volatile("cp.async.commit_group;"); }

__device__ __forceinline__ void mma16816(float c[4], uint32_t a0, uint32_t a1,
                                         uint32_t a2, uint32_t a3,
                                         uint32_t b0, uint32_t b1)
{
    asm volatile("mma.sync.aligned.m16n8k16.row.col.f32.bf16.bf16.f32 "
                 "{%0,%1,%2,%3}, {%4,%5,%6,%7}, {%8,%9}, {%0,%1,%2,%3};"
                 : "+f"(c[0]), "+f"(c[1]), "+f"(c[2]), "+f"(c[3])
                 : "r"(a0), "r"(a1), "r"(a2), "r"(a3), "r"(b0), "r"(b1));
}
__device__ __forceinline__ void ldsm4_a(uint32_t* r, uint32_t a)
{
    asm volatile("ldmatrix.sync.aligned.m8n8.x4.shared.b16 {%0,%1,%2,%3}, [%4];"
                 : "=r"(r[0]), "=r"(r[1]), "=r"(r[2]), "=r"(r[3]) : "r"(a));
}
__device__ __forceinline__ void ldsm4t_a(uint32_t* r, uint32_t a)
{
    asm volatile("ldmatrix.sync.aligned.m8n8.x4.trans.shared.b16 {%0,%1,%2,%3}, [%4];"
                 : "=r"(r[0]), "=r"(r[1]), "=r"(r[2]), "=r"(r[3]) : "r"(a));
}

// ---------------- LayerNorm -> hi/lo ----------------
__global__ __launch_bounds__(256) void ln_hilo_kernel(const float* __restrict__ x,
                                                      __nv_bfloat16* __restrict__ hi,
                                                      __nv_bfloat16* __restrict__ lo)
{
    long long base = (long long)blockIdx.x * 1024;
    float v4[4];
    float s = 0.f, ss = 0.f;
#pragma unroll
    for (int i = 0; i < 4; i++) {
        v4[i] = x[base + threadIdx.x + i * 256];
        s += v4[i]; ss += v4[i] * v4[i];
    }
    __shared__ float shs[32], shq[32];
    for (int o = 16; o; o >>= 1) {
        s  += __shfl_xor_sync(0xffffffffu, s,  o);
        ss += __shfl_xor_sync(0xffffffffu, ss, o);
    }
    int w = threadIdx.x >> 5, l = threadIdx.x & 31;
    if (l == 0) { shs[w] = s; shq[w] = ss; }
    __syncthreads();
    if (w == 0) {
        float a = (l < 8) ? shs[l] : 0.f;
        float b = (l < 8) ? shq[l] : 0.f;
        for (int o = 4; o; o >>= 1) {
            a += __shfl_xor_sync(0xffffffffu, a, o);
            b += __shfl_xor_sync(0xffffffffu, b, o);
        }
        if (l == 0) { shs[0] = a; shq[0] = b; }
    }
    __syncthreads();
    float mean = shs[0] * (1.0f / 1024.0f);
    float var  = shq[0] * (1.0f / 1024.0f) - mean * mean;
    float inv  = rsqrtf(var + 1e-6f);
#pragma unroll
    for (int i = 0; i < 4; i++) {
        float h = (v4[i] - mean) * inv;
        __nv_bfloat16 hh, ll;
        split_hilo(h, hh, ll);
        hi[base + threadIdx.x + i * 256] = hh;
        lo[base + threadIdx.x + i * 256] = ll;
    }
}

// ---------------- fp32 -> hi/lo split (weights / ctx), 4 elems/thread ----------------
__global__ __launch_bounds__(256) void split_kernel(const float* __restrict__ x,
                                                    __nv_bfloat16* __restrict__ hi,
                                                    __nv_bfloat16* __restrict__ lo)
{
    long long i = ((long long)blockIdx.x * 256 + threadIdx.x) * 4;
    float4 v = *reinterpret_cast<const float4*>(&x[i]);
    __nv_bfloat16 h[4], l[4];
    split_hilo(v.x, h[0], l[0]); split_hilo(v.y, h[1], l[1]);
    split_hilo(v.z, h[2], l[2]); split_hilo(v.w, h[3], l[3]);
    uint2 uh, ul;
    uh.x = ((uint32_t)*(uint16_t*)&h[1] << 16) | *(uint16_t*)&h[0];
    uh.y = ((uint32_t)*(uint16_t*)&h[3] << 16) | *(uint16_t*)&h[2];
    ul.x = ((uint32_t)*(uint16_t*)&l[1] << 16) | *(uint16_t*)&l[0];
    ul.y = ((uint32_t)*(uint16_t*)&l[3] << 16) | *(uint16_t*)&l[2];
    *reinterpret_cast<uint2*>(&hi[i]) = uh;
    *reinterpret_cast<uint2*>(&lo[i]) = ul;
}

// ---------------- bf16 hi/lo 3-term GEMM, 128x128 tile, BK=32, 3-stage cp.async ----
// C[M,N] = A @ B, A=[M,K] (Ah+Al), B=[K,N] (Bh+Bl), all bf16.
// MODE 0: fp32 out = acc + bias + res
// MODE 1: bf16 out = acc + bias
// MODE 2: hi/lo out = gelu(acc + bias)
template <int MODE>
__global__ __launch_bounds__(256) void gemm_bf3(
    const __nv_bfloat16* __restrict__ Ah, const __nv_bfloat16* __restrict__ Al,
    const __nv_bfloat16* __restrict__ Bh, const __nv_bfloat16* __restrict__ Bl,
    const float* __restrict__ bias, const float* __restrict__ res,
    void* __restrict__ out, void* __restrict__ out2, int K, int N)
{
    // smem layout per stage (bytes):
    //   A: 256 rows (128 hi | 128 lo) x pitch 40 bf16 -> 20480
    //   B:  64 rows ( 32 hi |  32 lo) x pitch 136 bf16 -> 17408
    constexpr int STAGE = 37888;
    extern __shared__ __align__(16) char smem[];
    const uint32_t sbase = smem_u32(smem);

    const int tid = threadIdx.x;
    const int w = tid >> 5, lane = tid & 31;
    const int grp = lane >> 3, lrow8 = lane & 7;
    const int wr = w >> 2, wc = w & 3;              // 2x4 warps; warp tile 64x32
    const int rbase = wr * 64, cbase = wc * 32;

    const __nv_bfloat16* Abh = Ah + (long long)blockIdx.y * 128 * K;
    const __nv_bfloat16* Abl = Al + (long long)blockIdx.y * 128 * K;
    const __nv_bfloat16* Bbh = Bh + blockIdx.x * 128;
    const __nv_bfloat16* Bbl = Bl + blockIdx.x * 128;

    auto load_stage = [&](int kt, int s) {
        uint32_t sb = sbase + s * STAGE;
#pragma unroll
        for (int j = 0; j < 4; j++) {               // A: 1024 16B chunks
            int idx = tid + j * 256;
            int t = idx >> 9, within = idx & 511;
            int row = within >> 2, c = within & 3;
            const __nv_bfloat16* g = (t ? Abl : Abh) + (long long)row * K + kt * 32 + c * 8;
            cp16(sb + ((t * 128 + row) * 40 + c * 8) * 2, g);
        }
#pragma unroll
        for (int j = 0; j < 4; j++) {               // B: 1024 16B chunks
            int idx = tid + j * 256;
            int t = idx >> 9, within = idx & 511;
            int row = within >> 4, c = within & 15;
            const __nv_bfloat16* g = (t ? Bbl : Bbh) + (long long)(kt * 32 + row) * N + c * 8;
            cp16(sb + 20480 + ((t * 32 + row) * 136 + c * 8) * 2, g);
        }
        cp_commit();
    };

    float acc[4][4][4];
#pragma unroll
    for (int i = 0; i < 4; i++)
#pragma unroll
        for (int j = 0; j < 4; j++)
#pragma unroll
            for (int e = 0; e < 4; e++) acc[i][j][e] = 0.f;

    const int KT = K >> 5;
    load_stage(0, 0);
    load_stage(1, 1);

    for (int kt = 0; kt < KT; kt++) {
        if (kt + 1 < KT) asm volatile("cp.async.wait_group 1;" ::: "memory");
        else             asm volatile("cp.async.wait_group 0;" ::: "memory");
        __syncthreads();
        if (kt + 2 < KT) load_stage(kt + 2, (kt + 2) % 3);

        const uint32_t Ab = sbase + (kt % 3) * STAGE;
        const uint32_t Bb = Ab + 20480;
#pragma unroll
        for (int kk = 0; kk < 32; kk += 16) {
            uint32_t ah[4][4], al[4][4];
#pragma unroll
            for (int i = 0; i < 4; i++) {
                uint32_t addr = Ab + ((rbase + i * 16 + (grp & 1) * 8 + lrow8) * 40 +
                                      kk + (grp & 2) * 4) * 2;
                ldsm4_a(ah[i], addr);
                ldsm4_a(al[i], addr + 128 * 40 * 2);
            }
            uint32_t bh[2][4], bl[2][4];
#pragma unroll
            for (int j = 0; j < 2; j++) {
                uint32_t addr = Bb + ((kk + (grp & 1) * 8 + lrow8) * 136 +
                                      cbase + j * 16 + (grp & 2) * 4) * 2;
                ldsm4t_a(bh[j], addr);
                ldsm4t_a(bl[j], addr + 32 * 136 * 2);
            }
#pragma unroll
            for (int i = 0; i < 4; i++)
#pragma unroll
                for (int jj = 0; jj < 4; jj++) {
                    uint32_t b0 = bh[jj >> 1][(jj & 1) * 2], b1 = bh[jj >> 1][(jj & 1) * 2 + 1];
                    mma16816(acc[i][jj], ah[i][0], ah[i][1], ah[i][2], ah[i][3], b0, b1);
                    mma16816(acc[i][jj], al[i][0], al[i][1], al[i][2], al[i][3], b0, b1);
                    uint32_t c0 = bl[jj >> 1][(jj & 1) * 2], c1 = bl[jj >> 1][(jj & 1) * 2 + 1];
                    mma16816(acc[i][jj], ah[i][0], ah[i][1], ah[i][2], ah[i][3], c0, c1);
                }
        }
    }

    // ---- epilogue straight from registers ----
    const int tr = lane >> 2, tc = (lane & 3) * 2;
#pragma unroll
    for (int i = 0; i < 4; i++) {
        long long gr0 = (long long)blockIdx.y * 128 + rbase + i * 16 + tr;
#pragma unroll
        for (int jj = 0; jj < 4; jj++) {
            int gc = blockIdx.x * 128 + cbase + jj * 8 + tc;
            float b0 = bias[gc], b1 = bias[gc + 1];
            float v0 = acc[i][jj][0] + b0, v1 = acc[i][jj][1] + b1;
            float v2 = acc[i][jj][2] + b0, v3 = acc[i][jj][3] + b1;
            if (MODE == 0) {
                float* fo = (float*)out;
                float2 r0 = *reinterpret_cast<const float2*>(&res[gr0 * N + gc]);
                float2 r1 = *reinterpret_cast<const float2*>(&res[(gr0 + 8) * N + gc]);
                *reinterpret_cast<float2*>(&fo[gr0 * N + gc]) =
                    make_float2(v0 + r0.x, v1 + r0.y);
                *reinterpret_cast<float2*>(&fo[(gr0 + 8) * N + gc]) =
                    make_float2(v2 + r1.x, v3 + r1.y);
            } else if (MODE == 1) {
                __nv_bfloat16* bo = (__nv_bfloat16*)out;
                *reinterpret_cast<uint32_t*>(&bo[gr0 * N + gc])       = packbf2(v0, v1);
                *reinterpret_cast<uint32_t*>(&bo[(gr0 + 8) * N + gc]) = packbf2(v2, v3);
            } else {
                float g[4] = { v0, v1, v2, v3 };
#pragma unroll
                for (int e = 0; e < 4; e++) {
                    float xx = g[e];
                    float tt = 0.7978845608028654f * (xx + 0.044715f * xx * xx * xx);
                    g[e] = 0.5f * xx * (1.0f + tanhf(tt));
                }
                __nv_bfloat16 h0, l0, h1, l1;
                __nv_bfloat16* ho = (__nv_bfloat16*)out;
                __nv_bfloat16* lo = (__nv_bfloat16*)out2;
                split_hilo(g[0], h0, l0); split_hilo(g[1], h1, l1);
                *reinterpret_cast<uint32_t*>(&ho[gr0 * N + gc]) =
                    ((uint32_t)*(uint16_t*)&h1 << 16) | *(uint16_t*)&h0;
                *reinterpret_cast<uint32_t*>(&lo[gr0 * N + gc]) =
                    ((uint32_t)*(uint16_t*)&l1 << 16) | *(uint16_t*)&l0;
                split_hilo(g[2], h0, l0); split_hilo(g[3], h1, l1);
                *reinterpret_cast<uint32_t*>(&ho[(gr0 + 8) * N + gc]) =
                    ((uint32_t)*(uint16_t*)&h1 << 16) | *(uint16_t*)&h0;
                *reinterpret_cast<uint32_t*>(&lo[(gr0 + 8) * N + gc]) =
                    ((uint32_t)*(uint16_t*)&l1 << 16) | *(uint16_t*)&l0;
            }
        }
    }
}

// ---------------- fused flash attention (bf16), hi/lo output ----------------
__global__ __launch_bounds__(128) void flash_kernel(
    const __nv_bfloat16* __restrict__ Qg, const __nv_bfloat16* __restrict__ Kg,
    const __nv_bfloat16* __restrict__ Vg,
    __nv_bfloat16* __restrict__ Ohi, __nv_bfloat16* __restrict__ Olo,
    int sq, int skv, int nk)
{
    constexpr int PD = 72;
    __shared__ __align__(16) __nv_bfloat16 Ks[64 * PD];
    __shared__ __align__(16) __nv_bfloat16 Vs[64 * PD];

    const int tid = threadIdx.x;
    const int w = tid >> 5, t = tid & 31;
    const int bh = blockIdx.y;
    const int b = bh >> 4, h = bh & 15;

    const long long qrow0 = (long long)b * 2048 + (long long)blockIdx.x * 128;
    const __nv_bfloat16* Qb = Qg + qrow0 * sq + h * 64;
    const __nv_bfloat16* Kb = Kg + (long long)b * nk * skv + h * 64;
    const __nv_bfloat16* Vb = Vg + (long long)b * nk * skv + h * 64;
    __nv_bfloat16* Obh = Ohi + qrow0 * 1024 + h * 64;
    __nv_bfloat16* Obl = Olo + qrow0 * 1024 + h * 64;

    const int qr = w * 32;
    const int tr = t >> 2, tc = (t & 3) * 2;

    uint32_t qa[2][4][4];
#pragma unroll
    for (int mt = 0; mt < 2; mt++) {
        int r0 = qr + mt * 16 + tr;
#pragma unroll
        for (int kc = 0; kc < 4; kc++) {
            int c0 = kc * 16 + tc;
            qa[mt][kc][0] = *reinterpret_cast<const uint32_t*>(&Qb[(long long)r0 * sq + c0]);
            qa[mt][kc][1] = *reinterpret_cast<const uint32_t*>(&Qb[(long long)(r0 + 8) * sq + c0]);
            qa[mt][kc][2] = *reinterpret_cast<const uint32_t*>(&Qb[(long long)r0 * sq + c0 + 8]);
            qa[mt][kc][3] = *reinterpret_cast<const uint32_t*>(&Qb[(long long)(r0 + 8) * sq + c0 + 8]);
        }
    }

    float o[2][8][4];
    float mrow[2][2], lrow[2][2];
#pragma unroll
    for (int mt = 0; mt < 2; mt++) {
        mrow[mt][0] = mrow[mt][1] = -1e30f;
        lrow[mt][0] = lrow[mt][1] = 0.f;
#pragma unroll
        for (int nb = 0; nb < 8; nb++)
#pragma unroll
            for (int e = 0; e < 4; e++) o[mt][nb][e] = 0.f;
    }

    const float CSC = 0.18033688011112042f;
    const int niter = nk >> 6;
    const int grp = t >> 3, lrow8 = t & 7;

    for (int kb = 0; kb < niter; kb++) {
        __syncthreads();
#pragma unroll
        for (int i = tid; i < 64 * 8; i += 128) {
            int r = i >> 3, c = i & 7;
            long long g = (long long)(kb * 64 + r) * skv + c * 8;
            *reinterpret_cast<uint4*>(&Ks[r * PD + c * 8]) =
                *reinterpret_cast<const uint4*>(&Kb[g]);
            *reinterpret_cast<uint4*>(&Vs[r * PD + c * 8]) =
                *reinterpret_cast<const uint4*>(&Vb[g]);
        }
        __syncthreads();

        float s[2][8][4];
#pragma unroll
        for (int mt = 0; mt < 2; mt++)
#pragma unroll
            for (int nb = 0; nb < 8; nb++)
#pragma unroll
                for (int e = 0; e < 4; e++) s[mt][nb][e] = 0.f;

#pragma unroll
        for (int kc = 0; kc < 4; kc++) {
#pragma unroll
            for (int nbp = 0; nbp < 4; nbp++) {
                uint32_t r[4];
                uint32_t addr = smem_u32(
                    &Ks[(nbp * 16 + (grp & 2) * 4 + lrow8) * PD + kc * 16 + (grp & 1) * 8]);
                ldsm4_a(r, addr);
#pragma unroll
                for (int mt = 0; mt < 2; mt++) {
                    mma16816(s[mt][2 * nbp],     qa[mt][kc][0], qa[mt][kc][1],
                             qa[mt][kc][2], qa[mt][kc][3], r[0], r[1]);
                    mma16816(s[mt][2 * nbp + 1], qa[mt][kc][0], qa[mt][kc][1],
                             qa[mt][kc][2], qa[mt][kc][3], r[2], r[3]);
                }
            }
        }

#pragma unroll
        for (int mt = 0; mt < 2; mt++) {
#pragma unroll
            for (int half = 0; half < 2; half++) {
                int e0 = 2 * half;
                float mx = -1e30f;
#pragma unroll
                for (int nb = 0; nb < 8; nb++)
                    mx = fmaxf(mx, fmaxf(s[mt][nb][e0], s[mt][nb][e0 + 1]));
                mx = fmaxf(mx, __shfl_xor_sync(0xffffffffu, mx, 1));
                mx = fmaxf(mx, __shfl_xor_sync(0xffffffffu, mx, 2));
                float newm = fmaxf(mrow[mt][half], mx);
                float alpha = exp2f((mrow[mt][half] - newm) * CSC);
                float sum = 0.f;
#pragma unroll
                for (int nb = 0; nb < 8; nb++) {
                    float p0 = exp2f((s[mt][nb][e0] - newm) * CSC);
                    float p1 = exp2f((s[mt][nb][e0 + 1] - newm) * CSC);
                    s[mt][nb][e0] = p0; s[mt][nb][e0 + 1] = p1;
                    sum += p0 + p1;
                }
                sum += __shfl_xor_sync(0xffffffffu, sum, 1);
                sum += __shfl_xor_sync(0xffffffffu, sum, 2);
                lrow[mt][half] = lrow[mt][half] * alpha + sum;
                mrow[mt][half] = newm;
#pragma unroll
                for (int nb = 0; nb < 8; nb++) {
                    o[mt][nb][e0]     *= alpha;
                    o[mt][nb][e0 + 1] *= alpha;
                }
            }
        }

#pragma unroll
        for (int kcP = 0; kcP < 4; kcP++) {
            uint32_t pa[2][4];
#pragma unroll
            for (int mt = 0; mt < 2; mt++) {
                pa[mt][0] = packbf2(s[mt][2 * kcP][0],     s[mt][2 * kcP][1]);
                pa[mt][1] = packbf2(s[mt][2 * kcP][2],     s[mt][2 * kcP][3]);
                pa[mt][2] = packbf2(s[mt][2 * kcP + 1][0], s[mt][2 * kcP + 1][1]);
                pa[mt][3] = packbf2(s[mt][2 * kcP + 1][2], s[mt][2 * kcP + 1][3]);
            }
#pragma unroll
            for (int nbp = 0; nbp < 4; nbp++) {
                uint32_t r[4];
                uint32_t addr = smem_u32(
                    &Vs[(kcP * 16 + (grp & 1) * 8 + lrow8) * PD + nbp * 16 + (grp & 2) * 4]);
                ldsm4t_a(r, addr);
#pragma unroll
                for (int mt = 0; mt < 2; mt++) {
                    mma16816(o[mt][2 * nbp],     pa[mt][0], pa[mt][1], pa[mt][2], pa[mt][3],
                             r[0], r[1]);
                    mma16816(o[mt][2 * nbp + 1], pa[mt][0], pa[mt][1], pa[mt][2], pa[mt][3],
                             r[2], r[3]);
                }
            }
        }
    }

#pragma unroll
    for (int mt = 0; mt < 2; mt++) {
        int r0 = qr + mt * 16 + tr;
        float inv0 = 1.0f / lrow[mt][0];
        float inv1 = 1.0f / lrow[mt][1];
#pragma unroll
        for (int nb = 0; nb < 8; nb++) {
            int col = nb * 8 + tc;
            float a0 = o[mt][nb][0] * inv0, a1 = o[mt][nb][1] * inv0;
            float b0 = o[mt][nb][2] * inv1, b1 = o[mt][nb][3] * inv1;
            __nv_bfloat16 h0, l0, h1, l1;
            split_hilo(a0, h0, l0); split_hilo(a1, h1, l1);
            *reinterpret_cast<uint32_t*>(&Obh[(long long)r0 * 1024 + col]) =
                ((uint32_t)*(uint16_t*)&h1 << 16) | *(uint16_t*)&h0;
            *reinterpret_cast<uint32_t*>(&Obl[(long long)r0 * 1024 + col]) =
                ((uint32_t)*(uint16_t*)&l1 << 16) | *(uint16_t*)&l0;
            split_hilo(b0, h0, l0); split_hilo(b1, h1, l1);
            *reinterpret_cast<uint32_t*>(&Obh[(long long)(r0 + 8) * 1024 + col]) =
                ((uint32_t)*(uint16_t*)&h1 << 16) | *(uint16_t*)&h0;
            *reinterpret_cast<uint32_t*>(&Obl[(long long)(r0 + 8) * 1024 + col]) =
                ((uint32_t)*(uint16_t*)&l1 << 16) | *(uint16_t*)&l0;
        }
    }
}

// ---------------- host ----------------
static void* devptr(const void* symbol)
{
    void* p = nullptr;
    cudaGetSymbolAddress(&p, symbol);
    return p;
}

extern "C" void kernel_launch(void* const* d_in, const int* in_sizes, int n_in,
                              void* d_out, int out_size)
{
    const float* x    = (const float*)d_in[0];
    const float* ctx  = (const float*)d_in[1];
    const float* Wqkv = (const float*)d_in[2];
    const float* bqkv = (const float*)d_in[3];
    const float* Wos  = (const float*)d_in[4];
    const float* bos  = (const float*)d_in[5];
    const float* Wq   = (const float*)d_in[6];
    const float* bq   = (const float*)d_in[7];
    const float* Wkv  = (const float*)d_in[8];
    const float* bkv  = (const float*)d_in[9];
    const float* Woc  = (const float*)d_in[10];
    const float* boc  = (const float*)d_in[11];
    const float* W1   = (const float*)d_in[12];
    const float* b1   = (const float*)d_in[13];
    const float* W2   = (const float*)d_in[14];
    const float* b2   = (const float*)d_in[15];
    float* out = (float*)d_out;

    __nv_bfloat16* wh  = (__nv_bfloat16*)devptr(g_w_hi);
    __nv_bfloat16* wl  = (__nv_bfloat16*)devptr(g_w_lo);
    __nv_bfloat16* lnh = (__nv_bfloat16*)devptr(g_lnh);
    __nv_bfloat16* lnl = (__nv_bfloat16*)devptr(g_lnl);
    __nv_bfloat16* ath = (__nv_bfloat16*)devptr(g_ath);
    __nv_bfloat16* atl = (__nv_bfloat16*)devptr(g_atl);
    __nv_bfloat16* cxh = (__nv_bfloat16*)devptr(g_cxh);
    __nv_bfloat16* cxl = (__nv_bfloat16*)devptr(g_cxl);
    __nv_bfloat16* mdh = (__nv_bfloat16*)devptr(g_mdh);
    __nv_bfloat16* mdl = (__nv_bfloat16*)devptr(g_mdl);
    __nv_bfloat16* qkv = (__nv_bfloat16*)devptr(g_qkv);
    __nv_bfloat16* q   = (__nv_bfloat16*)devptr(g_q);
    __nv_bfloat16* kv  = (__nv_bfloat16*)devptr(g_kv);
    float* x1 = (float*)devptr(g_x1);
    float* x2 = (float*)devptr(g_x2);

    const int SMEM = 3 * 37888;    // 113664 bytes
    cudaFuncSetAttribute(gemm_bf3<0>, cudaFuncAttributeMaxDynamicSharedMemorySize, SMEM);
    cudaFuncSetAttribute(gemm_bf3<1>, cudaFuncAttributeMaxDynamicSharedMemorySize, SMEM);
    cudaFuncSetAttribute(gemm_bf3<2>, cudaFuncAttributeMaxDynamicSharedMemorySize, SMEM);

    // ---- weight + ctx splits ----
    split_kernel<<<3145728 / 1024, 256>>>(Wqkv, wh + OFF_QKV, wl + OFF_QKV);
    split_kernel<<<1048576 / 1024, 256>>>(Wos,  wh + OFF_OS,  wl + OFF_OS);
    split_kernel<<<1048576 / 1024, 256>>>(Wq,   wh + OFF_Q,   wl + OFF_Q);
    split_kernel<<<2097152 / 1024, 256>>>(Wkv,  wh + OFF_KV,  wl + OFF_KV);
    split_kernel<<<1048576 / 1024, 256>>>(Woc,  wh + OFF_OC,  wl + OFF_OC);
    split_kernel<<<4194304 / 1024, 256>>>(W1,   wh + OFF_W1,  wl + OFF_W1);
    split_kernel<<<4194304 / 1024, 256>>>(W2,   wh + OFF_W2,  wl + OFF_W2);
    split_kernel<<<2097152 / 1024, 256>>>(ctx, cxh, cxl);

    // ---- self-attention ----
    ln_hilo_kernel<<<4096, 256>>>(x, lnh, lnl);
    gemm_bf3<1><<<dim3(24, 32), 256, SMEM>>>(lnh, lnl, wh + OFF_QKV, wl + OFF_QKV,
                                             bqkv, nullptr, qkv, nullptr, 1024, 3072);
    flash_kernel<<<dim3(16, 32), 128>>>(qkv, qkv + 1024, qkv + 2048, ath, atl,
                                        3072, 3072, 2048);
    gemm_bf3<0><<<dim3(8, 32), 256, SMEM>>>(ath, atl, wh + OFF_OS, wl + OFF_OS,
                                            bos, x, x1, nullptr, 1024, 1024);

    // ---- cross-attention ----
    ln_hilo_kernel<<<4096, 256>>>(x1, lnh, lnl);
    gemm_bf3<1><<<dim3(8, 32), 256, SMEM>>>(lnh, lnl, wh + OFF_Q, wl + OFF_Q,
                                            bq, nullptr, q, nullptr, 1024, 1024);
    gemm_bf3<1><<<dim3(16, 16), 256, SMEM>>>(cxh, cxl, wh + OFF_KV, wl + OFF_KV,
                                             bkv, nullptr, kv, nullptr, 1024, 2048);
    flash_kernel<<<dim3(16, 32), 128>>>(q, kv, kv + 1024, ath, atl, 1024, 2048, 1024);
    gemm_bf3<0><<<dim3(8, 32), 256, SMEM>>>(ath, atl, wh + OFF_OC, wl + OFF_OC,
                                            boc, x1, x2, nullptr, 1024, 1024);

    // ---- MLP ----
    ln_hilo_kernel<<<4096, 256>>>(x2, lnh, lnl);
    gemm_bf3<2><<<dim3(32, 32), 256, SMEM>>>(lnh, lnl, wh + OFF_W1, wl + OFF_W1,
                                             b1, nullptr, mdh, mdl, 1024, 4096);
    gemm_bf3<0><<<dim3(8, 32), 256, SMEM>>>(mdh, mdl, wh + OFF_W2, wl + OFF_W2,
                                            b2, x2, out, nullptr, 4096, 1024);
}